// round 9
// baseline (speedup 1.0000x reference)
#include <cuda_runtime.h>
#include <cuda_fp16.h>
#include <cstdint>

// GraphAttentionLayer: N=12288, IN_F=256, OUT_F=128, slope=0.2
// out = [h_prime (N x 128) | attention (N x N)] fp32.
//
//  k_pre    : h_t = h @ W in regs -> htT fp16 (transposed) + exp tables.
//  k_bits   : adj -> packed bitmask + folded denominators; full exp tables
//             preloaded in 98KB smem, flat streaming loop (no chunk barriers).
//  k_main   : grid 288 = 96 row-tiles x 3 j-thirds, 256 thr, 2 blocks/SM;
//             per-third exp tables staged in smem; P fragments in registers
//             (fp16, 1-term MMA), B via cp.async double-buffer + ldmatrix;
//             streaming attention stores; h_prime partials to scratch.
//  k_red    : sum 3 partials -> h_prime.

#define KN    12288
#define INF_  256
#define OUTF  128
#define NWORDS (KN / 32)     // 384
#define CH    128            // K-chunk
#define NSPLIT 3
#define NCL   (KN / CH / NSPLIT)   // 32 chunks per split
#define JSPAN (KN / NSPLIT)        // 4096

__device__ __half g_htT[(size_t)OUTF * KN];
__device__ __align__(16) float g_Es[KN], g_Es2[KN], g_Etgt[KN], g_Etgt2[KN];
__device__ float g_A[KN], g_B[KN];
__device__ __align__(16) uint32_t g_bits[(size_t)KN * NWORDS];
__device__ float g_part[(size_t)NSPLIT * KN * OUTF];

// ---------------- helpers ----------------
__device__ __forceinline__ uint32_t smem_u32(const void* p) {
    uint32_t a;
    asm("{ .reg .u64 t; cvta.to.shared.u64 t, %1; cvt.u32.u64 %0, t; }" : "=r"(a) : "l"(p));
    return a;
}
__device__ __forceinline__ uint32_t packh2(float p0, float p1) {
    uint32_t r;
    asm("cvt.rn.f16x2.f32 %0, %1, %2;" : "=r"(r) : "f"(p1), "f"(p0));
    return r;
}
__device__ __forceinline__ void stcs2(float* p, float a, float b) {
    asm volatile("st.global.cs.v2.f32 [%0], {%1, %2};" :: "l"(p), "f"(a), "f"(b) : "memory");
}
__device__ __forceinline__ int4 ldcs4(const int4* p) {
    int4 v;
    asm volatile("ld.global.cs.nc.v4.s32 {%0,%1,%2,%3}, [%4];"
                 : "=r"(v.x), "=r"(v.y), "=r"(v.z), "=r"(v.w) : "l"(p));
    return v;
}

#define MMA16816(d, a0, a1, a2, a3, b0, b1) \
    asm volatile( \
        "mma.sync.aligned.m16n8k16.row.col.f32.f16.f16.f32 " \
        "{%0,%1,%2,%3}, {%4,%5,%6,%7}, {%8,%9}, {%0,%1,%2,%3};" \
        : "+f"((d).x), "+f"((d).y), "+f"((d).z), "+f"((d).w) \
        : "r"(a0), "r"(a1), "r"(a2), "r"(a3), "r"(b0), "r"(b1))

#define LDMX4(r0, r1, r2, r3, ad) \
    asm volatile("ldmatrix.sync.aligned.m8n8.x4.shared.b16 {%0,%1,%2,%3}, [%4];" \
                 : "=r"(r0), "=r"(r1), "=r"(r2), "=r"(r3) : "r"(ad))

#define CP16(dst, src) \
    asm volatile("cp.async.cg.shared.global [%0], [%1], 16;" :: "r"(dst), "l"(src) : "memory")
#define CP_COMMIT() asm volatile("cp.async.commit_group;" ::: "memory")
#define CP_WAIT1()  asm volatile("cp.async.wait_group 1;" ::: "memory")
#define CP_WAIT0()  asm volatile("cp.async.wait_group 0;" ::: "memory")

// ---------------- K1: fused h@W -> htT fp16 + exp tables ----------------
__global__ void __launch_bounds__(256) k_pre(const float* __restrict__ h,
                                             const float* __restrict__ W,
                                             const float* __restrict__ a) {
    __shared__ float h_s[8 * INF_];
    __shared__ float red[8][8];
    int t = threadIdx.x;
    int r0 = blockIdx.x * 8;
    for (int idx = t; idx < 8 * INF_; idx += 256)
        h_s[idx] = h[(size_t)r0 * INF_ + idx];
    __syncthreads();
    int c  = t & 127;
    int rg = t >> 7;
    float acc[4] = {0.f, 0.f, 0.f, 0.f};
    for (int k = 0; k < INF_; k++) {
        float w = W[k * OUTF + c];
#pragma unroll
        for (int rr = 0; rr < 4; rr++)
            acc[rr] = fmaf(h_s[(rg * 4 + rr) * INF_ + k], w, acc[rr]);
    }
    *(uint2*)(g_htT + (size_t)c * KN + r0 + rg * 4) =
        make_uint2(packh2(acc[0], acc[1]), packh2(acc[2], acc[3]));

    float av = a[c], av2 = a[OUTF + c];
    float s[8];
#pragma unroll
    for (int rr = 0; rr < 4; rr++) {
        s[rr * 2]     = acc[rr] * av;
        s[rr * 2 + 1] = acc[rr] * av2;
    }
#pragma unroll
    for (int o = 16; o > 0; o >>= 1)
#pragma unroll
        for (int i = 0; i < 8; i++)
            s[i] += __shfl_down_sync(0xFFFFFFFFu, s[i], o);
    int w = t >> 5, l = t & 31;
    if (l == 0)
#pragma unroll
        for (int i = 0; i < 8; i++) red[w][i] = s[i];
    __syncthreads();
    if (t < 16) {
        int rho = t >> 1, which = t & 1;
        int rg2 = rho >> 2, rr = rho & 3;
        float v = red[rg2 * 4 + 0][rr * 2 + which] + red[rg2 * 4 + 1][rr * 2 + which]
                + red[rg2 * 4 + 2][rr * 2 + which] + red[rg2 * 4 + 3][rr * 2 + which];
        int r = r0 + rho;
        if (which == 0) { g_Es[r]   = expf(v); g_Es2[r]   = expf(0.2f * v); }
        else            { g_Etgt[r] = expf(v); g_Etgt2[r] = expf(0.2f * v); }
    }
}

// ---------------- Kbits: bitmask + denominators (full smem tables) ----------
#define SMEM_BITS (2 * KN * 4)   // 98304
__global__ void __launch_bounds__(256) k_bits(const int* __restrict__ adj) {
    extern __shared__ __align__(16) float sE[];
    float* sE1 = sE;
    float* sE2 = sE + KN;
    int t = threadIdx.x;
    // preload full exp tables
#pragma unroll
    for (int i = 0; i < KN / 1024; i++) {
        ((float4*)sE1)[i * 256 + t] = ((const float4*)g_Etgt)[i * 256 + t];
        ((float4*)sE2)[i * 256 + t] = ((const float4*)g_Etgt2)[i * 256 + t];
    }
    __syncthreads();

    int l = t & 31;
    int r = blockIdx.x * 8 + (t >> 5);
    float Es = g_Es[r], Es2 = g_Es2[r];
    const int4* __restrict__ arow = (const int4*)(adj + (size_t)r * KN);
    uint32_t* __restrict__ brow = g_bits + (size_t)r * NWORDS;
    const int sh = (l & 7) * 4;
    float ls0 = 0.f, ls1 = 0.f, ls2 = 0.f, ls3 = 0.f;

#pragma unroll 4
    for (int it = 0; it < KN / 128; it++) {     // 96 iterations, 128 j per warp
        int j = it * 128 + l * 4;
        int4 m = ldcs4(arow + it * 32 + l);
        float4 e1 = *(const float4*)&sE1[j];
        float4 e2 = *(const float4*)&sE2[j];
        uint32_t nib = 0;
        if (m.x) { nib |= 1u; ls0 += fmaxf(Es * e1.x, Es2 * e2.x); }
        if (m.y) { nib |= 2u; ls1 += fmaxf(Es * e1.y, Es2 * e2.y); }
        if (m.z) { nib |= 4u; ls2 += fmaxf(Es * e1.z, Es2 * e2.z); }
        if (m.w) { nib |= 8u; ls3 += fmaxf(Es * e1.w, Es2 * e2.w); }
        uint32_t word = nib << sh;
        word |= __shfl_xor_sync(0xFFFFFFFFu, word, 1);
        word |= __shfl_xor_sync(0xFFFFFFFFu, word, 2);
        word |= __shfl_xor_sync(0xFFFFFFFFu, word, 4);
        if ((l & 7) == 0) brow[it * 4 + (l >> 3)] = word;
    }
    float lsum = (ls0 + ls1) + (ls2 + ls3);
#pragma unroll
    for (int o = 16; o > 0; o >>= 1) lsum += __shfl_down_sync(0xFFFFFFFFu, lsum, o);
    if (l == 0) {
        float inv = 1.0f / lsum;
        g_A[r] = Es * inv;
        g_B[r] = Es2 * inv;
    }
}

// ---------------- K2: fused P-gen + mma.sync GEMM (smem e-tables) --------
#define ROWSTRIDE 272
#define VERBYTES  (128 * ROWSTRIDE)          // 34816
#define SMEM_E    (JSPAN * 2 * 4)            // 32768
#define SMEM_MAIN (2 * VERBYTES + SMEM_E)    // 102400

__global__ void __launch_bounds__(256, 2) k_main(float* __restrict__ out) {
    extern __shared__ char sm[];
    const uint32_t smb = smem_u32(sm);
    float* __restrict__ sE1 = (float*)(sm + 2 * VERBYTES);
    float* __restrict__ sE2 = sE1 + JSPAN;
    const int t  = threadIdx.x;
    const int w  = t >> 5, l = t & 31;
    const int g  = l >> 2, tq = l & 3;
    const int ti = blockIdx.x / NSPLIT;     // row tile
    const int js = blockIdx.x % NSPLIT;     // j third
    const int i0 = ti * 128;
    const int jbase = js * JSPAN;
    const int row0 = i0 + w * 16 + g;       // warp owns 16 rows
    const int row1 = row0 + 8;

    // stage this third's exp tables (32KB)
#pragma unroll
    for (int i = 0; i < JSPAN / 1024; i++) {
        ((float4*)sE1)[i * 256 + t] = ((const float4*)(g_Etgt  + jbase))[i * 256 + t];
        ((float4*)sE2)[i * 256 + t] = ((const float4*)(g_Etgt2 + jbase))[i * 256 + t];
    }

    const float aA0 = g_A[row0], bB0 = g_B[row0];
    const float aA1 = g_A[row1], bB1 = g_B[row1];
    float* __restrict__ attn0 = out + (size_t)KN * OUTF + (size_t)row0 * KN;
    float* __restrict__ attn1 = out + (size_t)KN * OUTF + (size_t)row1 * KN;
    const uint4* __restrict__ bits0 = (const uint4*)(g_bits + (size_t)row0 * NWORDS) + js * NCL;
    const uint4* __restrict__ bits1 = (const uint4*)(g_bits + (size_t)row1 * NWORDS) + js * NCL;

    const int cpr = t >> 4;          // 0..15
    const int cpk = t & 15;
    const uint32_t lmrow = ((l >> 4) & 1) * 8 + (l & 7);
    const uint32_t lmoff = lmrow * ROWSTRIDE + ((l >> 3) & 1) * 16;

    float4 acc[16];
#pragma unroll
    for (int i = 0; i < 16; i++) acc[i] = make_float4(0.f, 0.f, 0.f, 0.f);

    // prologue: chunk 0 -> buf 0
#pragma unroll
    for (int i = 0; i < 8; i++) {
        int row = cpr + i * 16;
        CP16(smb + row * ROWSTRIDE + cpk * 16,
             g_htT + (size_t)row * KN + jbase + cpk * 8);
    }
    CP_COMMIT();

    for (int c = 0; c < NCL; c++) {
        const int buf = c & 1;
        if (c + 1 < NCL) {
            const int jn = jbase + (c + 1) * CH;
            const uint32_t dstb = smb + (buf ^ 1) * VERBYTES;
#pragma unroll
            for (int i = 0; i < 8; i++) {
                int row = cpr + i * 16;
                CP16(dstb + row * ROWSTRIDE + cpk * 16,
                     g_htT + (size_t)row * KN + jn + cpk * 8);
            }
            CP_COMMIT();
            CP_WAIT1();
        } else {
            CP_WAIT0();
        }
        __syncthreads();

        const uint4 w0 = bits0[c];
        const uint4 w1 = bits1[c];
        const uint32_t lmb = smb + buf * VERBYTES + lmoff;

#pragma unroll 2
        for (int kk = 0; kk < 8; kk++) {
            const int jl = c * CH + kk * 16;           // local (in-third) index
            const int j  = jbase + jl;                  // global index
            float2 e1a = *(const float2*)&sE1[jl + 2 * tq];
            float2 e1b = *(const float2*)&sE1[jl + 2 * tq + 8];
            float2 e2a = *(const float2*)&sE2[jl + 2 * tq];
            float2 e2b = *(const float2*)&sE2[jl + 2 * tq + 8];
            const uint32_t bwa = ((const uint32_t*)&w0)[kk >> 1] >> ((kk & 1) * 16);
            const uint32_t bwb = ((const uint32_t*)&w1)[kk >> 1] >> ((kk & 1) * 16);

            float p00 = (bwa >> (2 * tq))     & 1 ? fmaxf(aA0 * e1a.x, bB0 * e2a.x) : 0.f;
            float p01 = (bwa >> (2 * tq + 1)) & 1 ? fmaxf(aA0 * e1a.y, bB0 * e2a.y) : 0.f;
            float p02 = (bwa >> (2 * tq + 8)) & 1 ? fmaxf(aA0 * e1b.x, bB0 * e2b.x) : 0.f;
            float p03 = (bwa >> (2 * tq + 9)) & 1 ? fmaxf(aA0 * e1b.y, bB0 * e2b.y) : 0.f;
            float p10 = (bwb >> (2 * tq))     & 1 ? fmaxf(aA1 * e1a.x, bB1 * e2a.x) : 0.f;
            float p11 = (bwb >> (2 * tq + 1)) & 1 ? fmaxf(aA1 * e1a.y, bB1 * e2a.y) : 0.f;
            float p12 = (bwb >> (2 * tq + 8)) & 1 ? fmaxf(aA1 * e1b.x, bB1 * e2b.x) : 0.f;
            float p13 = (bwb >> (2 * tq + 9)) & 1 ? fmaxf(aA1 * e1b.y, bB1 * e2b.y) : 0.f;

            stcs2(attn0 + j + 2 * tq,     p00, p01);
            stcs2(attn0 + j + 2 * tq + 8, p02, p03);
            stcs2(attn1 + j + 2 * tq,     p10, p11);
            stcs2(attn1 + j + 2 * tq + 8, p12, p13);

            const uint32_t ah0 = packh2(p00, p01);
            const uint32_t ah1 = packh2(p10, p11);
            const uint32_t ah2 = packh2(p02, p03);
            const uint32_t ah3 = packh2(p12, p13);

            const uint32_t lmk = lmb + kk * 32;
#pragma unroll
            for (int np = 0; np < 8; np++) {
                uint32_t bh0, bh1, bh2, bh3;
                LDMX4(bh0, bh1, bh2, bh3, lmk + np * (16 * ROWSTRIDE));
                MMA16816(acc[2 * np],     ah0, ah1, ah2, ah3, bh0, bh1);
                MMA16816(acc[2 * np + 1], ah0, ah1, ah2, ah3, bh2, bh3);
            }
        }
        __syncthreads();
    }

    // epilogue: h_prime partial for this j-third
    float* __restrict__ part = g_part + (size_t)js * KN * OUTF;
#pragma unroll
    for (int nt = 0; nt < 16; nt++) {
        int cc = nt * 8 + 2 * tq;
        *(float2*)(part + (size_t)row0 * OUTF + cc) = make_float2(acc[nt].x, acc[nt].y);
        *(float2*)(part + (size_t)row1 * OUTF + cc) = make_float2(acc[nt].z, acc[nt].w);
    }
}

// ---------------- K3: reduce partials ----------------
__global__ void __launch_bounds__(256) k_red(float* __restrict__ out) {
    const size_t SZ = (size_t)KN * OUTF;
    size_t idx = ((size_t)blockIdx.x * 256 + threadIdx.x) * 4;
    float4 a = *(const float4*)(g_part + idx);
    float4 b = *(const float4*)(g_part + SZ + idx);
    float4 c = *(const float4*)(g_part + 2 * SZ + idx);
    *(float4*)(out + idx) = make_float4(a.x + b.x + c.x, a.y + b.y + c.y,
                                        a.z + b.z + c.z, a.w + b.w + c.w);
}

extern "C" void kernel_launch(void* const* d_in, const int* in_sizes, int n_in,
                              void* d_out, int out_size) {
    const float* h   = (const float*)d_in[0];
    const int*   adj = (const int*)d_in[1];
    const float* W   = (const float*)d_in[2];
    const float* a   = (const float*)d_in[3];
    float* out = (float*)d_out;

    cudaFuncSetAttribute(k_main, cudaFuncAttributeMaxDynamicSharedMemorySize, SMEM_MAIN);
    cudaFuncSetAttribute(k_bits, cudaFuncAttributeMaxDynamicSharedMemorySize, SMEM_BITS);

    k_pre<<<KN / 8, 256>>>(h, W, a);
    k_bits<<<KN / 8, 256, SMEM_BITS>>>(adj);
    k_main<<<(KN / 128) * NSPLIT, 256, SMEM_MAIN>>>(out);
    k_red<<<(KN * OUTF) / (256 * 4), 256>>>(out);
}

// round 10
// speedup vs baseline: 1.1134x; 1.1134x over previous
#include <cuda_runtime.h>
#include <cuda_fp16.h>
#include <cstdint>

// GraphAttentionLayer: N=12288, IN_F=256, OUT_F=128, slope=0.2
// out = [h_prime (N x 128) | attention (N x N)] fp32.
//
//  k_pre    : h_t = h @ W in regs -> htT fp16 (transposed) + exp tables.
//  k_bits   : adj -> packed bitmask + folded denominators (8KB chunked smem,
//             high occupancy — R8 version).
//  k_main   : grid 288 = 96 row-tiles x 3 j-thirds, 256 thr, 2 blocks/SM;
//             per-third exp tables staged in smem; P fragments in registers
//             (fp16, 1-term MMA), B via cp.async double-buffer + ldmatrix;
//             streaming attention stores; h_prime partials to scratch.
//  k_red    : sum 3 partials -> h_prime.

#define KN    12288
#define INF_  256
#define OUTF  128
#define NWORDS (KN / 32)     // 384
#define CH    128            // K-chunk
#define NSPLIT 3
#define NCL   (KN / CH / NSPLIT)   // 32 chunks per split
#define JSPAN (KN / NSPLIT)        // 4096

__device__ __half g_htT[(size_t)OUTF * KN];
__device__ __align__(16) float g_Es[KN], g_Es2[KN], g_Etgt[KN], g_Etgt2[KN];
__device__ float g_A[KN], g_B[KN];
__device__ __align__(16) uint32_t g_bits[(size_t)KN * NWORDS];
__device__ float g_part[(size_t)NSPLIT * KN * OUTF];

// ---------------- helpers ----------------
__device__ __forceinline__ uint32_t smem_u32(const void* p) {
    uint32_t a;
    asm("{ .reg .u64 t; cvta.to.shared.u64 t, %1; cvt.u32.u64 %0, t; }" : "=r"(a) : "l"(p));
    return a;
}
__device__ __forceinline__ uint32_t packh2(float p0, float p1) {
    uint32_t r;
    asm("cvt.rn.f16x2.f32 %0, %1, %2;" : "=r"(r) : "f"(p1), "f"(p0));
    return r;
}
__device__ __forceinline__ void stcs2(float* p, float a, float b) {
    asm volatile("st.global.cs.v2.f32 [%0], {%1, %2};" :: "l"(p), "f"(a), "f"(b) : "memory");
}
__device__ __forceinline__ int4 ldcs4(const int4* p) {
    int4 v;
    asm volatile("ld.global.cs.nc.v4.s32 {%0,%1,%2,%3}, [%4];"
                 : "=r"(v.x), "=r"(v.y), "=r"(v.z), "=r"(v.w) : "l"(p));
    return v;
}

#define MMA16816(d, a0, a1, a2, a3, b0, b1) \
    asm volatile( \
        "mma.sync.aligned.m16n8k16.row.col.f32.f16.f16.f32 " \
        "{%0,%1,%2,%3}, {%4,%5,%6,%7}, {%8,%9}, {%0,%1,%2,%3};" \
        : "+f"((d).x), "+f"((d).y), "+f"((d).z), "+f"((d).w) \
        : "r"(a0), "r"(a1), "r"(a2), "r"(a3), "r"(b0), "r"(b1))

#define LDMX4(r0, r1, r2, r3, ad) \
    asm volatile("ldmatrix.sync.aligned.m8n8.x4.shared.b16 {%0,%1,%2,%3}, [%4];" \
                 : "=r"(r0), "=r"(r1), "=r"(r2), "=r"(r3) : "r"(ad))

#define CP16(dst, src) \
    asm volatile("cp.async.cg.shared.global [%0], [%1], 16;" :: "r"(dst), "l"(src) : "memory")
#define CP_COMMIT() asm volatile("cp.async.commit_group;" ::: "memory")
#define CP_WAIT1()  asm volatile("cp.async.wait_group 1;" ::: "memory")
#define CP_WAIT0()  asm volatile("cp.async.wait_group 0;" ::: "memory")

// ---------------- K1: fused h@W -> htT fp16 + exp tables ----------------
__global__ void __launch_bounds__(256) k_pre(const float* __restrict__ h,
                                             const float* __restrict__ W,
                                             const float* __restrict__ a) {
    __shared__ float h_s[8 * INF_];
    __shared__ float red[8][8];
    int t = threadIdx.x;
    int r0 = blockIdx.x * 8;
    for (int idx = t; idx < 8 * INF_; idx += 256)
        h_s[idx] = h[(size_t)r0 * INF_ + idx];
    __syncthreads();
    int c  = t & 127;
    int rg = t >> 7;
    float acc[4] = {0.f, 0.f, 0.f, 0.f};
    for (int k = 0; k < INF_; k++) {
        float w = W[k * OUTF + c];
#pragma unroll
        for (int rr = 0; rr < 4; rr++)
            acc[rr] = fmaf(h_s[(rg * 4 + rr) * INF_ + k], w, acc[rr]);
    }
    *(uint2*)(g_htT + (size_t)c * KN + r0 + rg * 4) =
        make_uint2(packh2(acc[0], acc[1]), packh2(acc[2], acc[3]));

    float av = a[c], av2 = a[OUTF + c];
    float s[8];
#pragma unroll
    for (int rr = 0; rr < 4; rr++) {
        s[rr * 2]     = acc[rr] * av;
        s[rr * 2 + 1] = acc[rr] * av2;
    }
#pragma unroll
    for (int o = 16; o > 0; o >>= 1)
#pragma unroll
        for (int i = 0; i < 8; i++)
            s[i] += __shfl_down_sync(0xFFFFFFFFu, s[i], o);
    int w = t >> 5, l = t & 31;
    if (l == 0)
#pragma unroll
        for (int i = 0; i < 8; i++) red[w][i] = s[i];
    __syncthreads();
    if (t < 16) {
        int rho = t >> 1, which = t & 1;
        int rg2 = rho >> 2, rr = rho & 3;
        float v = red[rg2 * 4 + 0][rr * 2 + which] + red[rg2 * 4 + 1][rr * 2 + which]
                + red[rg2 * 4 + 2][rr * 2 + which] + red[rg2 * 4 + 3][rr * 2 + which];
        int r = r0 + rho;
        if (which == 0) { g_Es[r]   = expf(v); g_Es2[r]   = expf(0.2f * v); }
        else            { g_Etgt[r] = expf(v); g_Etgt2[r] = expf(0.2f * v); }
    }
}

// ---------------- Kbits: bitmask + denominators (R8 chunked, high occ) ------
__global__ void __launch_bounds__(256) k_bits(const int* __restrict__ adj) {
    __shared__ __align__(16) float sE1[1024], sE2[1024];
    int t = threadIdx.x;
    int l = t & 31;
    int r = blockIdx.x * 8 + (t >> 5);
    float Es = g_Es[r], Es2 = g_Es2[r];
    const int4* __restrict__ arow = (const int4*)(adj + (size_t)r * KN);
    uint32_t* __restrict__ brow = g_bits + (size_t)r * NWORDS;
    const int sh = (l & 7) * 4;
    float ls0 = 0.f, ls1 = 0.f, ls2 = 0.f, ls3 = 0.f;

    for (int jc = 0; jc < KN / 1024; jc++) {    // 12 chunks
        __syncthreads();
        *(float4*)&sE1[t * 4] = *(const float4*)(g_Etgt  + jc * 1024 + t * 4);
        *(float4*)&sE2[t * 4] = *(const float4*)(g_Etgt2 + jc * 1024 + t * 4);
        __syncthreads();
#pragma unroll
        for (int it = 0; it < 8; it++) {        // 128 j per warp per it
            int4 m = ldcs4(arow + jc * 256 + it * 32 + l);
            float4 e1 = *(const float4*)&sE1[it * 128 + l * 4];
            float4 e2 = *(const float4*)&sE2[it * 128 + l * 4];
            uint32_t nib = 0;
            if (m.x) { nib |= 1u; ls0 += fmaxf(Es * e1.x, Es2 * e2.x); }
            if (m.y) { nib |= 2u; ls1 += fmaxf(Es * e1.y, Es2 * e2.y); }
            if (m.z) { nib |= 4u; ls2 += fmaxf(Es * e1.z, Es2 * e2.z); }
            if (m.w) { nib |= 8u; ls3 += fmaxf(Es * e1.w, Es2 * e2.w); }
            uint32_t word = nib << sh;
            word |= __shfl_xor_sync(0xFFFFFFFFu, word, 1);
            word |= __shfl_xor_sync(0xFFFFFFFFu, word, 2);
            word |= __shfl_xor_sync(0xFFFFFFFFu, word, 4);
            if ((l & 7) == 0) brow[jc * 32 + it * 4 + (l >> 3)] = word;
        }
    }
    float lsum = (ls0 + ls1) + (ls2 + ls3);
#pragma unroll
    for (int o = 16; o > 0; o >>= 1) lsum += __shfl_down_sync(0xFFFFFFFFu, lsum, o);
    if (l == 0) {
        float inv = 1.0f / lsum;
        g_A[r] = Es * inv;
        g_B[r] = Es2 * inv;
    }
}

// ---------------- K2: fused P-gen + mma.sync GEMM (smem e-tables) --------
#define ROWSTRIDE 272
#define VERBYTES  (128 * ROWSTRIDE)          // 34816
#define SMEM_E    (JSPAN * 2 * 4)            // 32768
#define SMEM_MAIN (2 * VERBYTES + SMEM_E)    // 102400

__global__ void __launch_bounds__(256, 2) k_main(float* __restrict__ out) {
    extern __shared__ char sm[];
    const uint32_t smb = smem_u32(sm);
    float* __restrict__ sE1 = (float*)(sm + 2 * VERBYTES);
    float* __restrict__ sE2 = sE1 + JSPAN;
    const int t  = threadIdx.x;
    const int w  = t >> 5, l = t & 31;
    const int g  = l >> 2, tq = l & 3;
    const int ti = blockIdx.x / NSPLIT;     // row tile
    const int js = blockIdx.x % NSPLIT;     // j third
    const int i0 = ti * 128;
    const int jbase = js * JSPAN;
    const int row0 = i0 + w * 16 + g;       // warp owns 16 rows
    const int row1 = row0 + 8;

    // stage this third's exp tables (32KB)
#pragma unroll
    for (int i = 0; i < JSPAN / 1024; i++) {
        ((float4*)sE1)[i * 256 + t] = ((const float4*)(g_Etgt  + jbase))[i * 256 + t];
        ((float4*)sE2)[i * 256 + t] = ((const float4*)(g_Etgt2 + jbase))[i * 256 + t];
    }

    const float aA0 = g_A[row0], bB0 = g_B[row0];
    const float aA1 = g_A[row1], bB1 = g_B[row1];
    float* __restrict__ attn0 = out + (size_t)KN * OUTF + (size_t)row0 * KN;
    float* __restrict__ attn1 = out + (size_t)KN * OUTF + (size_t)row1 * KN;
    const uint4* __restrict__ bits0 = (const uint4*)(g_bits + (size_t)row0 * NWORDS) + js * NCL;
    const uint4* __restrict__ bits1 = (const uint4*)(g_bits + (size_t)row1 * NWORDS) + js * NCL;

    const int cpr = t >> 4;          // 0..15
    const int cpk = t & 15;
    const uint32_t lmrow = ((l >> 4) & 1) * 8 + (l & 7);
    const uint32_t lmoff = lmrow * ROWSTRIDE + ((l >> 3) & 1) * 16;

    float4 acc[16];
#pragma unroll
    for (int i = 0; i < 16; i++) acc[i] = make_float4(0.f, 0.f, 0.f, 0.f);

    // prologue: chunk 0 -> buf 0
#pragma unroll
    for (int i = 0; i < 8; i++) {
        int row = cpr + i * 16;
        CP16(smb + row * ROWSTRIDE + cpk * 16,
             g_htT + (size_t)row * KN + jbase + cpk * 8);
    }
    CP_COMMIT();

    for (int c = 0; c < NCL; c++) {
        const int buf = c & 1;
        // hoist bits loads above the wait/barrier (no smem dependence)
        const uint4 w0 = bits0[c];
        const uint4 w1 = bits1[c];
        if (c + 1 < NCL) {
            const int jn = jbase + (c + 1) * CH;
            const uint32_t dstb = smb + (buf ^ 1) * VERBYTES;
#pragma unroll
            for (int i = 0; i < 8; i++) {
                int row = cpr + i * 16;
                CP16(dstb + row * ROWSTRIDE + cpk * 16,
                     g_htT + (size_t)row * KN + jn + cpk * 8);
            }
            CP_COMMIT();
            CP_WAIT1();
        } else {
            CP_WAIT0();
        }
        __syncthreads();

        const uint32_t lmb = smb + buf * VERBYTES + lmoff;

#pragma unroll 2
        for (int kk = 0; kk < 8; kk++) {
            const int jl = c * CH + kk * 16;           // local (in-third) index
            const int j  = jbase + jl;                  // global index
            float2 e1a = *(const float2*)&sE1[jl + 2 * tq];
            float2 e1b = *(const float2*)&sE1[jl + 2 * tq + 8];
            float2 e2a = *(const float2*)&sE2[jl + 2 * tq];
            float2 e2b = *(const float2*)&sE2[jl + 2 * tq + 8];
            const uint32_t bwa = ((const uint32_t*)&w0)[kk >> 1] >> ((kk & 1) * 16);
            const uint32_t bwb = ((const uint32_t*)&w1)[kk >> 1] >> ((kk & 1) * 16);

            float p00 = (bwa >> (2 * tq))     & 1 ? fmaxf(aA0 * e1a.x, bB0 * e2a.x) : 0.f;
            float p01 = (bwa >> (2 * tq + 1)) & 1 ? fmaxf(aA0 * e1a.y, bB0 * e2a.y) : 0.f;
            float p02 = (bwa >> (2 * tq + 8)) & 1 ? fmaxf(aA0 * e1b.x, bB0 * e2b.x) : 0.f;
            float p03 = (bwa >> (2 * tq + 9)) & 1 ? fmaxf(aA0 * e1b.y, bB0 * e2b.y) : 0.f;
            float p10 = (bwb >> (2 * tq))     & 1 ? fmaxf(aA1 * e1a.x, bB1 * e2a.x) : 0.f;
            float p11 = (bwb >> (2 * tq + 1)) & 1 ? fmaxf(aA1 * e1a.y, bB1 * e2a.y) : 0.f;
            float p12 = (bwb >> (2 * tq + 8)) & 1 ? fmaxf(aA1 * e1b.x, bB1 * e2b.x) : 0.f;
            float p13 = (bwb >> (2 * tq + 9)) & 1 ? fmaxf(aA1 * e1b.y, bB1 * e2b.y) : 0.f;

            stcs2(attn0 + j + 2 * tq,     p00, p01);
            stcs2(attn0 + j + 2 * tq + 8, p02, p03);
            stcs2(attn1 + j + 2 * tq,     p10, p11);
            stcs2(attn1 + j + 2 * tq + 8, p12, p13);

            const uint32_t ah0 = packh2(p00, p01);
            const uint32_t ah1 = packh2(p10, p11);
            const uint32_t ah2 = packh2(p02, p03);
            const uint32_t ah3 = packh2(p12, p13);

            const uint32_t lmk = lmb + kk * 32;
#pragma unroll
            for (int np = 0; np < 8; np++) {
                uint32_t bh0, bh1, bh2, bh3;
                LDMX4(bh0, bh1, bh2, bh3, lmk + np * (16 * ROWSTRIDE));
                MMA16816(acc[2 * np],     ah0, ah1, ah2, ah3, bh0, bh1);
                MMA16816(acc[2 * np + 1], ah0, ah1, ah2, ah3, bh2, bh3);
            }
        }
        __syncthreads();
    }

    // epilogue: h_prime partial for this j-third
    float* __restrict__ part = g_part + (size_t)js * KN * OUTF;
#pragma unroll
    for (int nt = 0; nt < 16; nt++) {
        int cc = nt * 8 + 2 * tq;
        *(float2*)(part + (size_t)row0 * OUTF + cc) = make_float2(acc[nt].x, acc[nt].y);
        *(float2*)(part + (size_t)row1 * OUTF + cc) = make_float2(acc[nt].z, acc[nt].w);
    }
}

// ---------------- K3: reduce partials ----------------
__global__ void __launch_bounds__(256) k_red(float* __restrict__ out) {
    const size_t SZ = (size_t)KN * OUTF;
    size_t idx = ((size_t)blockIdx.x * 256 + threadIdx.x) * 4;
    float4 a = *(const float4*)(g_part + idx);
    float4 b = *(const float4*)(g_part + SZ + idx);
    float4 c = *(const float4*)(g_part + 2 * SZ + idx);
    *(float4*)(out + idx) = make_float4(a.x + b.x + c.x, a.y + b.y + c.y,
                                        a.z + b.z + c.z, a.w + b.w + c.w);
}

extern "C" void kernel_launch(void* const* d_in, const int* in_sizes, int n_in,
                              void* d_out, int out_size) {
    const float* h   = (const float*)d_in[0];
    const int*   adj = (const int*)d_in[1];
    const float* W   = (const float*)d_in[2];
    const float* a   = (const float*)d_in[3];
    float* out = (float*)d_out;

    cudaFuncSetAttribute(k_main, cudaFuncAttributeMaxDynamicSharedMemorySize, SMEM_MAIN);

    k_pre<<<KN / 8, 256>>>(h, W, a);
    k_bits<<<KN / 8, 256>>>(adj);
    k_main<<<(KN / 128) * NSPLIT, 256, SMEM_MAIN>>>(out);
    k_red<<<(KN * OUTF) / (256 * 4), 256>>>(out);
}

// round 11
// speedup vs baseline: 1.1336x; 1.0182x over previous
#include <cuda_runtime.h>
#include <cuda_fp16.h>
#include <cstdint>

// GraphAttentionLayer: N=12288, IN_F=256, OUT_F=128, slope=0.2
// out = [h_prime (N x 128) | attention (N x N)] fp32.
//
//  k_pre    : h_t = h @ W in regs -> htT fp16 (transposed) + exp tables.
//  k_bits   : adj -> packed bitmask + folded denominators (R8 chunked).
//  k_main   : grid 288 = 96 row-tiles x 3 j-thirds, 256 thr, 2 blocks/SM;
//             chunk body phase-split: (A) P-gen for all 8 kk -> ah[8][4],
//             attention stores batched; (B) MMA sweep with 1-deep LDSM
//             prefetch. B via cp.async double-buffer + ldmatrix.
//  k_red    : sum 3 partials -> h_prime.

#define KN    12288
#define INF_  256
#define OUTF  128
#define NWORDS (KN / 32)     // 384
#define CH    128            // K-chunk
#define NSPLIT 3
#define NCL   (KN / CH / NSPLIT)   // 32 chunks per split
#define JSPAN (KN / NSPLIT)        // 4096

__device__ __half g_htT[(size_t)OUTF * KN];
__device__ __align__(16) float g_Es[KN], g_Es2[KN], g_Etgt[KN], g_Etgt2[KN];
__device__ float g_A[KN], g_B[KN];
__device__ __align__(16) uint32_t g_bits[(size_t)KN * NWORDS];
__device__ float g_part[(size_t)NSPLIT * KN * OUTF];

// ---------------- helpers ----------------
__device__ __forceinline__ uint32_t smem_u32(const void* p) {
    uint32_t a;
    asm("{ .reg .u64 t; cvta.to.shared.u64 t, %1; cvt.u32.u64 %0, t; }" : "=r"(a) : "l"(p));
    return a;
}
__device__ __forceinline__ uint32_t packh2(float p0, float p1) {
    uint32_t r;
    asm("cvt.rn.f16x2.f32 %0, %1, %2;" : "=r"(r) : "f"(p1), "f"(p0));
    return r;
}
// streaming store, NO memory clobber (independent write-once data)
__device__ __forceinline__ void stcs2(float* p, float a, float b) {
    asm volatile("st.global.cs.v2.f32 [%0], {%1, %2};" :: "l"(p), "f"(a), "f"(b));
}
__device__ __forceinline__ int4 ldcs4(const int4* p) {
    int4 v;
    asm volatile("ld.global.cs.nc.v4.s32 {%0,%1,%2,%3}, [%4];"
                 : "=r"(v.x), "=r"(v.y), "=r"(v.z), "=r"(v.w) : "l"(p));
    return v;
}

#define MMA16816(d, a0, a1, a2, a3, b0, b1) \
    asm volatile( \
        "mma.sync.aligned.m16n8k16.row.col.f32.f16.f16.f32 " \
        "{%0,%1,%2,%3}, {%4,%5,%6,%7}, {%8,%9}, {%0,%1,%2,%3};" \
        : "+f"((d).x), "+f"((d).y), "+f"((d).z), "+f"((d).w) \
        : "r"(a0), "r"(a1), "r"(a2), "r"(a3), "r"(b0), "r"(b1))

#define LDMX4(r0, r1, r2, r3, ad) \
    asm volatile("ldmatrix.sync.aligned.m8n8.x4.shared.b16 {%0,%1,%2,%3}, [%4];" \
                 : "=r"(r0), "=r"(r1), "=r"(r2), "=r"(r3) : "r"(ad))

#define CP16(dst, src) \
    asm volatile("cp.async.cg.shared.global [%0], [%1], 16;" :: "r"(dst), "l"(src) : "memory")
#define CP_COMMIT() asm volatile("cp.async.commit_group;" ::: "memory")
#define CP_WAIT1()  asm volatile("cp.async.wait_group 1;" ::: "memory")
#define CP_WAIT0()  asm volatile("cp.async.wait_group 0;" ::: "memory")

// ---------------- K1: fused h@W -> htT fp16 + exp tables ----------------
__global__ void __launch_bounds__(256) k_pre(const float* __restrict__ h,
                                             const float* __restrict__ W,
                                             const float* __restrict__ a) {
    __shared__ float h_s[8 * INF_];
    __shared__ float red[8][8];
    int t = threadIdx.x;
    int r0 = blockIdx.x * 8;
    for (int idx = t; idx < 8 * INF_; idx += 256)
        h_s[idx] = h[(size_t)r0 * INF_ + idx];
    __syncthreads();
    int c  = t & 127;
    int rg = t >> 7;
    float acc[4] = {0.f, 0.f, 0.f, 0.f};
    for (int k = 0; k < INF_; k++) {
        float w = W[k * OUTF + c];
#pragma unroll
        for (int rr = 0; rr < 4; rr++)
            acc[rr] = fmaf(h_s[(rg * 4 + rr) * INF_ + k], w, acc[rr]);
    }
    *(uint2*)(g_htT + (size_t)c * KN + r0 + rg * 4) =
        make_uint2(packh2(acc[0], acc[1]), packh2(acc[2], acc[3]));

    float av = a[c], av2 = a[OUTF + c];
    float s[8];
#pragma unroll
    for (int rr = 0; rr < 4; rr++) {
        s[rr * 2]     = acc[rr] * av;
        s[rr * 2 + 1] = acc[rr] * av2;
    }
#pragma unroll
    for (int o = 16; o > 0; o >>= 1)
#pragma unroll
        for (int i = 0; i < 8; i++)
            s[i] += __shfl_down_sync(0xFFFFFFFFu, s[i], o);
    int w = t >> 5, l = t & 31;
    if (l == 0)
#pragma unroll
        for (int i = 0; i < 8; i++) red[w][i] = s[i];
    __syncthreads();
    if (t < 16) {
        int rho = t >> 1, which = t & 1;
        int rg2 = rho >> 2, rr = rho & 3;
        float v = red[rg2 * 4 + 0][rr * 2 + which] + red[rg2 * 4 + 1][rr * 2 + which]
                + red[rg2 * 4 + 2][rr * 2 + which] + red[rg2 * 4 + 3][rr * 2 + which];
        int r = r0 + rho;
        if (which == 0) { g_Es[r]   = expf(v); g_Es2[r]   = expf(0.2f * v); }
        else            { g_Etgt[r] = expf(v); g_Etgt2[r] = expf(0.2f * v); }
    }
}

// ---------------- Kbits: bitmask + denominators (R8 chunked) ------
__global__ void __launch_bounds__(256) k_bits(const int* __restrict__ adj) {
    __shared__ __align__(16) float sE1[1024], sE2[1024];
    int t = threadIdx.x;
    int l = t & 31;
    int r = blockIdx.x * 8 + (t >> 5);
    float Es = g_Es[r], Es2 = g_Es2[r];
    const int4* __restrict__ arow = (const int4*)(adj + (size_t)r * KN);
    uint32_t* __restrict__ brow = g_bits + (size_t)r * NWORDS;
    const int sh = (l & 7) * 4;
    float ls0 = 0.f, ls1 = 0.f, ls2 = 0.f, ls3 = 0.f;

    for (int jc = 0; jc < KN / 1024; jc++) {    // 12 chunks
        __syncthreads();
        *(float4*)&sE1[t * 4] = *(const float4*)(g_Etgt  + jc * 1024 + t * 4);
        *(float4*)&sE2[t * 4] = *(const float4*)(g_Etgt2 + jc * 1024 + t * 4);
        __syncthreads();
#pragma unroll
        for (int it = 0; it < 8; it++) {        // 128 j per warp per it
            int4 m = ldcs4(arow + jc * 256 + it * 32 + l);
            float4 e1 = *(const float4*)&sE1[it * 128 + l * 4];
            float4 e2 = *(const float4*)&sE2[it * 128 + l * 4];
            uint32_t nib = 0;
            if (m.x) { nib |= 1u; ls0 += fmaxf(Es * e1.x, Es2 * e2.x); }
            if (m.y) { nib |= 2u; ls1 += fmaxf(Es * e1.y, Es2 * e2.y); }
            if (m.z) { nib |= 4u; ls2 += fmaxf(Es * e1.z, Es2 * e2.z); }
            if (m.w) { nib |= 8u; ls3 += fmaxf(Es * e1.w, Es2 * e2.w); }
            uint32_t word = nib << sh;
            word |= __shfl_xor_sync(0xFFFFFFFFu, word, 1);
            word |= __shfl_xor_sync(0xFFFFFFFFu, word, 2);
            word |= __shfl_xor_sync(0xFFFFFFFFu, word, 4);
            if ((l & 7) == 0) brow[jc * 32 + it * 4 + (l >> 3)] = word;
        }
    }
    float lsum = (ls0 + ls1) + (ls2 + ls3);
#pragma unroll
    for (int o = 16; o > 0; o >>= 1) lsum += __shfl_down_sync(0xFFFFFFFFu, lsum, o);
    if (l == 0) {
        float inv = 1.0f / lsum;
        g_A[r] = Es * inv;
        g_B[r] = Es2 * inv;
    }
}

// ---------------- K2: fused P-gen + mma.sync GEMM (phase-split) --------
#define ROWSTRIDE 272
#define VERBYTES  (128 * ROWSTRIDE)   // 34816
#define SMEM_MAIN (2 * VERBYTES)      // 69632

__global__ void __launch_bounds__(256, 2) k_main(float* __restrict__ out) {
    extern __shared__ char sm[];
    const uint32_t smb = smem_u32(sm);
    const int t  = threadIdx.x;
    const int w  = t >> 5, l = t & 31;
    const int g  = l >> 2, tq = l & 3;
    const int ti = blockIdx.x / NSPLIT;     // row tile
    const int js = blockIdx.x % NSPLIT;     // j third
    const int i0 = ti * 128;
    const int jbase = js * JSPAN;
    const int row0 = i0 + w * 16 + g;       // warp owns 16 rows
    const int row1 = row0 + 8;

    const float aA0 = g_A[row0], bB0 = g_B[row0];
    const float aA1 = g_A[row1], bB1 = g_B[row1];
    float* __restrict__ attn0 = out + (size_t)KN * OUTF + (size_t)row0 * KN;
    float* __restrict__ attn1 = out + (size_t)KN * OUTF + (size_t)row1 * KN;
    const uint4* __restrict__ bits0 = (const uint4*)(g_bits + (size_t)row0 * NWORDS) + js * NCL;
    const uint4* __restrict__ bits1 = (const uint4*)(g_bits + (size_t)row1 * NWORDS) + js * NCL;

    const int cpr = t >> 4;          // 0..15
    const int cpk = t & 15;
    const uint32_t lmrow = ((l >> 4) & 1) * 8 + (l & 7);
    const uint32_t lmoff = lmrow * ROWSTRIDE + ((l >> 3) & 1) * 16;

    float4 acc[16];
#pragma unroll
    for (int i = 0; i < 16; i++) acc[i] = make_float4(0.f, 0.f, 0.f, 0.f);

    // prologue: chunk 0 -> buf 0
#pragma unroll
    for (int i = 0; i < 8; i++) {
        int row = cpr + i * 16;
        CP16(smb + row * ROWSTRIDE + cpk * 16,
             g_htT + (size_t)row * KN + jbase + cpk * 8);
    }
    CP_COMMIT();

    for (int c = 0; c < NCL; c++) {
        const int buf = c & 1;
        const uint4 w0 = bits0[c];
        const uint4 w1 = bits1[c];
        if (c + 1 < NCL) {
            const int jn = jbase + (c + 1) * CH;
            const uint32_t dstb = smb + (buf ^ 1) * VERBYTES;
#pragma unroll
            for (int i = 0; i < 8; i++) {
                int row = cpr + i * 16;
                CP16(dstb + row * ROWSTRIDE + cpk * 16,
                     g_htT + (size_t)row * KN + jn + cpk * 8);
            }
            CP_COMMIT();
            CP_WAIT1();
        } else {
            CP_WAIT0();
        }
        __syncthreads();

        // ---- Phase A: P-gen for all 8 kk; pack fragments; store attention ----
        uint32_t ah[8][4];
#pragma unroll
        for (int kk = 0; kk < 8; kk++) {
            const int j = jbase + c * CH + kk * 16;
            float2 e1a = *(const float2*)(g_Etgt  + j + 2 * tq);
            float2 e1b = *(const float2*)(g_Etgt  + j + 2 * tq + 8);
            float2 e2a = *(const float2*)(g_Etgt2 + j + 2 * tq);
            float2 e2b = *(const float2*)(g_Etgt2 + j + 2 * tq + 8);
            const uint32_t bwa = ((const uint32_t*)&w0)[kk >> 1] >> ((kk & 1) * 16);
            const uint32_t bwb = ((const uint32_t*)&w1)[kk >> 1] >> ((kk & 1) * 16);

            float p00 = (bwa >> (2 * tq))     & 1 ? fmaxf(aA0 * e1a.x, bB0 * e2a.x) : 0.f;
            float p01 = (bwa >> (2 * tq + 1)) & 1 ? fmaxf(aA0 * e1a.y, bB0 * e2a.y) : 0.f;
            float p02 = (bwa >> (2 * tq + 8)) & 1 ? fmaxf(aA0 * e1b.x, bB0 * e2b.x) : 0.f;
            float p03 = (bwa >> (2 * tq + 9)) & 1 ? fmaxf(aA0 * e1b.y, bB0 * e2b.y) : 0.f;
            float p10 = (bwb >> (2 * tq))     & 1 ? fmaxf(aA1 * e1a.x, bB1 * e2a.x) : 0.f;
            float p11 = (bwb >> (2 * tq + 1)) & 1 ? fmaxf(aA1 * e1a.y, bB1 * e2a.y) : 0.f;
            float p12 = (bwb >> (2 * tq + 8)) & 1 ? fmaxf(aA1 * e1b.x, bB1 * e2b.x) : 0.f;
            float p13 = (bwb >> (2 * tq + 9)) & 1 ? fmaxf(aA1 * e1b.y, bB1 * e2b.y) : 0.f;

            stcs2(attn0 + j + 2 * tq,     p00, p01);
            stcs2(attn0 + j + 2 * tq + 8, p02, p03);
            stcs2(attn1 + j + 2 * tq,     p10, p11);
            stcs2(attn1 + j + 2 * tq + 8, p12, p13);

            ah[kk][0] = packh2(p00, p01);
            ah[kk][1] = packh2(p10, p11);
            ah[kk][2] = packh2(p02, p03);
            ah[kk][3] = packh2(p12, p13);
        }

        // ---- Phase B: MMA sweep with 1-deep LDSM prefetch ----
        const uint32_t lmb = smb + buf * VERBYTES + lmoff;
#pragma unroll
        for (int np = 0; np < 8; np++) {
            const uint32_t npb = lmb + np * (16 * ROWSTRIDE);
            uint32_t b0, b1, b2, b3;
            LDMX4(b0, b1, b2, b3, npb);
#pragma unroll
            for (int kk = 0; kk < 8; kk++) {
                uint32_t n0, n1, n2, n3;
                if (kk < 7) { LDMX4(n0, n1, n2, n3, npb + (kk + 1) * 32); }
                MMA16816(acc[2 * np],     ah[kk][0], ah[kk][1], ah[kk][2], ah[kk][3], b0, b1);
                MMA16816(acc[2 * np + 1], ah[kk][0], ah[kk][1], ah[kk][2], ah[kk][3], b2, b3);
                if (kk < 7) { b0 = n0; b1 = n1; b2 = n2; b3 = n3; }
            }
        }
        __syncthreads();
    }

    // epilogue: h_prime partial for this j-third
    float* __restrict__ part = g_part + (size_t)js * KN * OUTF;
#pragma unroll
    for (int nt = 0; nt < 16; nt++) {
        int cc = nt * 8 + 2 * tq;
        *(float2*)(part + (size_t)row0 * OUTF + cc) = make_float2(acc[nt].x, acc[nt].y);
        *(float2*)(part + (size_t)row1 * OUTF + cc) = make_float2(acc[nt].z, acc[nt].w);
    }
}

// ---------------- K3: reduce partials ----------------
__global__ void __launch_bounds__(256) k_red(float* __restrict__ out) {
    const size_t SZ = (size_t)KN * OUTF;
    size_t idx = ((size_t)blockIdx.x * 256 + threadIdx.x) * 4;
    float4 a = *(const float4*)(g_part + idx);
    float4 b = *(const float4*)(g_part + SZ + idx);
    float4 c = *(const float4*)(g_part + 2 * SZ + idx);
    *(float4*)(out + idx) = make_float4(a.x + b.x + c.x, a.y + b.y + c.y,
                                        a.z + b.z + c.z, a.w + b.w + c.w);
}

extern "C" void kernel_launch(void* const* d_in, const int* in_sizes, int n_in,
                              void* d_out, int out_size) {
    const float* h   = (const float*)d_in[0];
    const int*   adj = (const int*)d_in[1];
    const float* W   = (const float*)d_in[2];
    const float* a   = (const float*)d_in[3];
    float* out = (float*)d_out;

    cudaFuncSetAttribute(k_main, cudaFuncAttributeMaxDynamicSharedMemorySize, SMEM_MAIN);

    k_pre<<<KN / 8, 256>>>(h, W, a);
    k_bits<<<KN / 8, 256>>>(adj);
    k_main<<<(KN / 128) * NSPLIT, 256, SMEM_MAIN>>>(out);
    k_red<<<(KN * OUTF) / (256 * 4), 256>>>(out);
}

// round 12
// speedup vs baseline: 1.1875x; 1.0475x over previous
#include <cuda_runtime.h>
#include <cuda_fp16.h>
#include <cstdint>

// GraphAttentionLayer: N=12288, IN_F=256, OUT_F=128, slope=0.2
// out = [h_prime (N x 128) | attention (N x N)] fp32.
//
//  k_pre    : h_t = h @ W in regs -> htT fp16 (transposed, k-PERMUTED) + exp
//             tables. Permutation pi maps k-pairs {2t,2t+8} <-> j {4t..4t+3}
//             within each 16-group so MMA threads own 4 contiguous j.
//  k_bits   : adj -> packed bitmask + folded denominators (R8 chunked).
//  k_main   : grid 288 = 96 row-tiles x 3 j-thirds, 256 thr, 2 blocks/SM;
//             phase A: P-gen with float4 e-loads + v4 attention stores;
//             phase B: kk-outer/np-inner MMA sweep, 1-deep LDSM prefetch.
//  k_red    : sum 3 partials -> h_prime.

#define KN    12288
#define INF_  256
#define OUTF  128
#define NWORDS (KN / 32)     // 384
#define CH    128            // K-chunk
#define NSPLIT 3
#define NCL   (KN / CH / NSPLIT)   // 32 chunks per split
#define JSPAN (KN / NSPLIT)        // 4096

__device__ __half g_htT[(size_t)OUTF * KN];   // k-permuted layout
__device__ __align__(16) float g_Es[KN], g_Es2[KN], g_Etgt[KN], g_Etgt2[KN];
__device__ float g_A[KN], g_B[KN];
__device__ __align__(16) uint32_t g_bits[(size_t)KN * NWORDS];
__device__ float g_part[(size_t)NSPLIT * KN * OUTF];

// ---------------- helpers ----------------
__device__ __forceinline__ uint32_t smem_u32(const void* p) {
    uint32_t a;
    asm("{ .reg .u64 t; cvta.to.shared.u64 t, %1; cvt.u32.u64 %0, t; }" : "=r"(a) : "l"(p));
    return a;
}
__device__ __forceinline__ uint32_t packh2(float p0, float p1) {
    uint32_t r;
    asm("cvt.rn.f16x2.f32 %0, %1, %2;" : "=r"(r) : "f"(p1), "f"(p0));
    return r;
}
__device__ __forceinline__ void stcs4(float* p, float a, float b, float c, float d) {
    asm volatile("st.global.cs.v4.f32 [%0], {%1, %2, %3, %4};"
                 :: "l"(p), "f"(a), "f"(b), "f"(c), "f"(d));
}
__device__ __forceinline__ int4 ldcs4(const int4* p) {
    int4 v;
    asm volatile("ld.global.cs.nc.v4.s32 {%0,%1,%2,%3}, [%4];"
                 : "=r"(v.x), "=r"(v.y), "=r"(v.z), "=r"(v.w) : "l"(p));
    return v;
}

#define MMA16816(d, a0, a1, a2, a3, b0, b1) \
    asm volatile( \
        "mma.sync.aligned.m16n8k16.row.col.f32.f16.f16.f32 " \
        "{%0,%1,%2,%3}, {%4,%5,%6,%7}, {%8,%9}, {%0,%1,%2,%3};" \
        : "+f"((d).x), "+f"((d).y), "+f"((d).z), "+f"((d).w) \
        : "r"(a0), "r"(a1), "r"(a2), "r"(a3), "r"(b0), "r"(b1))

#define LDMX4(r0, r1, r2, r3, ad) \
    asm volatile("ldmatrix.sync.aligned.m8n8.x4.shared.b16 {%0,%1,%2,%3}, [%4];" \
                 : "=r"(r0), "=r"(r1), "=r"(r2), "=r"(r3) : "r"(ad))

#define CP16(dst, src) \
    asm volatile("cp.async.cg.shared.global [%0], [%1], 16;" :: "r"(dst), "l"(src) : "memory")
#define CP_COMMIT() asm volatile("cp.async.commit_group;" ::: "memory")
#define CP_WAIT1()  asm volatile("cp.async.wait_group 1;" ::: "memory")
#define CP_WAIT0()  asm volatile("cp.async.wait_group 0;" ::: "memory")

// ---------------- K1: fused h@W -> permuted htT fp16 + exp tables -----------
__global__ void __launch_bounds__(256) k_pre(const float* __restrict__ h,
                                             const float* __restrict__ W,
                                             const float* __restrict__ a) {
    __shared__ float h_s[8 * INF_];
    __shared__ float red[8][8];
    int t = threadIdx.x;
    int r0 = blockIdx.x * 8;
    for (int idx = t; idx < 8 * INF_; idx += 256)
        h_s[idx] = h[(size_t)r0 * INF_ + idx];
    __syncthreads();
    int c  = t & 127;
    int rg = t >> 7;
    float acc[4] = {0.f, 0.f, 0.f, 0.f};
    for (int k = 0; k < INF_; k++) {
        float w = W[k * OUTF + c];
#pragma unroll
        for (int rr = 0; rr < 4; rr++)
            acc[rr] = fmaf(h_s[(rg * 4 + rr) * INF_ + k], w, acc[rr]);
    }
    // permuted store: 4 consecutive j (= one t-group) -> k-pairs {2T, 2T+8}
    {
        int jj  = r0 + rg * 4;           // first of 4 consecutive j
        int grp = jj & ~15;              // 16-group base
        int T   = (jj & 15) >> 2;        // 0..3
        __half* dst = g_htT + (size_t)c * KN + grp;
        *(uint32_t*)(dst + 2 * T)     = packh2(acc[0], acc[1]);
        *(uint32_t*)(dst + 2 * T + 8) = packh2(acc[2], acc[3]);
    }

    float av = a[c], av2 = a[OUTF + c];
    float s[8];
#pragma unroll
    for (int rr = 0; rr < 4; rr++) {
        s[rr * 2]     = acc[rr] * av;
        s[rr * 2 + 1] = acc[rr] * av2;
    }
#pragma unroll
    for (int o = 16; o > 0; o >>= 1)
#pragma unroll
        for (int i = 0; i < 8; i++)
            s[i] += __shfl_down_sync(0xFFFFFFFFu, s[i], o);
    int w = t >> 5, l = t & 31;
    if (l == 0)
#pragma unroll
        for (int i = 0; i < 8; i++) red[w][i] = s[i];
    __syncthreads();
    if (t < 16) {
        int rho = t >> 1, which = t & 1;
        int rg2 = rho >> 2, rr = rho & 3;
        float v = red[rg2 * 4 + 0][rr * 2 + which] + red[rg2 * 4 + 1][rr * 2 + which]
                + red[rg2 * 4 + 2][rr * 2 + which] + red[rg2 * 4 + 3][rr * 2 + which];
        int r = r0 + rho;
        if (which == 0) { g_Es[r]   = expf(v); g_Es2[r]   = expf(0.2f * v); }
        else            { g_Etgt[r] = expf(v); g_Etgt2[r] = expf(0.2f * v); }
    }
}

// ---------------- Kbits: bitmask + denominators (R8 chunked) ------
__global__ void __launch_bounds__(256) k_bits(const int* __restrict__ adj) {
    __shared__ __align__(16) float sE1[1024], sE2[1024];
    int t = threadIdx.x;
    int l = t & 31;
    int r = blockIdx.x * 8 + (t >> 5);
    float Es = g_Es[r], Es2 = g_Es2[r];
    const int4* __restrict__ arow = (const int4*)(adj + (size_t)r * KN);
    uint32_t* __restrict__ brow = g_bits + (size_t)r * NWORDS;
    const int sh = (l & 7) * 4;
    float ls0 = 0.f, ls1 = 0.f, ls2 = 0.f, ls3 = 0.f;

    for (int jc = 0; jc < KN / 1024; jc++) {    // 12 chunks
        __syncthreads();
        *(float4*)&sE1[t * 4] = *(const float4*)(g_Etgt  + jc * 1024 + t * 4);
        *(float4*)&sE2[t * 4] = *(const float4*)(g_Etgt2 + jc * 1024 + t * 4);
        __syncthreads();
#pragma unroll
        for (int it = 0; it < 8; it++) {        // 128 j per warp per it
            int4 m = ldcs4(arow + jc * 256 + it * 32 + l);
            float4 e1 = *(const float4*)&sE1[it * 128 + l * 4];
            float4 e2 = *(const float4*)&sE2[it * 128 + l * 4];
            uint32_t nib = 0;
            if (m.x) { nib |= 1u; ls0 += fmaxf(Es * e1.x, Es2 * e2.x); }
            if (m.y) { nib |= 2u; ls1 += fmaxf(Es * e1.y, Es2 * e2.y); }
            if (m.z) { nib |= 4u; ls2 += fmaxf(Es * e1.z, Es2 * e2.z); }
            if (m.w) { nib |= 8u; ls3 += fmaxf(Es * e1.w, Es2 * e2.w); }
            uint32_t word = nib << sh;
            word |= __shfl_xor_sync(0xFFFFFFFFu, word, 1);
            word |= __shfl_xor_sync(0xFFFFFFFFu, word, 2);
            word |= __shfl_xor_sync(0xFFFFFFFFu, word, 4);
            if ((l & 7) == 0) brow[jc * 32 + it * 4 + (l >> 3)] = word;
        }
    }
    float lsum = (ls0 + ls1) + (ls2 + ls3);
#pragma unroll
    for (int o = 16; o > 0; o >>= 1) lsum += __shfl_down_sync(0xFFFFFFFFu, lsum, o);
    if (l == 0) {
        float inv = 1.0f / lsum;
        g_A[r] = Es * inv;
        g_B[r] = Es2 * inv;
    }
}

// ---------------- K2: fused P-gen + mma.sync GEMM (permuted-k) --------
#define ROWSTRIDE 272
#define VERBYTES  (128 * ROWSTRIDE)   // 34816
#define SMEM_MAIN (2 * VERBYTES)      // 69632

__global__ void __launch_bounds__(256, 2) k_main(float* __restrict__ out) {
    extern __shared__ char sm[];
    const uint32_t smb = smem_u32(sm);
    const int t  = threadIdx.x;
    const int w  = t >> 5, l = t & 31;
    const int g  = l >> 2, tq = l & 3;
    const int ti = blockIdx.x / NSPLIT;     // row tile
    const int js = blockIdx.x % NSPLIT;     // j third
    const int i0 = ti * 128;
    const int jbase = js * JSPAN;
    const int row0 = i0 + w * 16 + g;       // warp owns 16 rows
    const int row1 = row0 + 8;

    const float aA0 = g_A[row0], bB0 = g_B[row0];
    const float aA1 = g_A[row1], bB1 = g_B[row1];
    float* __restrict__ attn0 = out + (size_t)KN * OUTF + (size_t)row0 * KN;
    float* __restrict__ attn1 = out + (size_t)KN * OUTF + (size_t)row1 * KN;
    const uint4* __restrict__ bits0 = (const uint4*)(g_bits + (size_t)row0 * NWORDS) + js * NCL;
    const uint4* __restrict__ bits1 = (const uint4*)(g_bits + (size_t)row1 * NWORDS) + js * NCL;

    const int cpr = t >> 4;          // 0..15
    const int cpk = t & 15;
    const uint32_t lmrow = ((l >> 4) & 1) * 8 + (l & 7);
    const uint32_t lmoff = lmrow * ROWSTRIDE + ((l >> 3) & 1) * 16;

    float4 acc[16];
#pragma unroll
    for (int i = 0; i < 16; i++) acc[i] = make_float4(0.f, 0.f, 0.f, 0.f);

    // prologue: chunk 0 -> buf 0
#pragma unroll
    for (int i = 0; i < 8; i++) {
        int row = cpr + i * 16;
        CP16(smb + row * ROWSTRIDE + cpk * 16,
             g_htT + (size_t)row * KN + jbase + cpk * 8);
    }
    CP_COMMIT();

    for (int c = 0; c < NCL; c++) {
        const int buf = c & 1;
        const uint4 w0 = bits0[c];
        const uint4 w1 = bits1[c];
        if (c + 1 < NCL) {
            const int jn = jbase + (c + 1) * CH;
            const uint32_t dstb = smb + (buf ^ 1) * VERBYTES;
#pragma unroll
            for (int i = 0; i < 8; i++) {
                int row = cpr + i * 16;
                CP16(dstb + row * ROWSTRIDE + cpk * 16,
                     g_htT + (size_t)row * KN + jn + cpk * 8);
            }
            CP_COMMIT();
            CP_WAIT1();
        } else {
            CP_WAIT0();
        }
        __syncthreads();

        // ---- Phase A: P-gen, 4 contiguous j per thread (permuted-k) ----
        uint32_t ah[8][4];
#pragma unroll
        for (int kk = 0; kk < 8; kk++) {
            const int j = jbase + c * CH + kk * 16 + 4 * tq;
            float4 e1 = *(const float4*)(g_Etgt  + j);
            float4 e2 = *(const float4*)(g_Etgt2 + j);
            const uint32_t nib0 = (((const uint32_t*)&w0)[kk >> 1] >> ((kk & 1) * 16 + 4 * tq));
            const uint32_t nib1 = (((const uint32_t*)&w1)[kk >> 1] >> ((kk & 1) * 16 + 4 * tq));

            float p00 = nib0 & 1 ? fmaxf(aA0 * e1.x, bB0 * e2.x) : 0.f;
            float p01 = nib0 & 2 ? fmaxf(aA0 * e1.y, bB0 * e2.y) : 0.f;
            float p02 = nib0 & 4 ? fmaxf(aA0 * e1.z, bB0 * e2.z) : 0.f;
            float p03 = nib0 & 8 ? fmaxf(aA0 * e1.w, bB0 * e2.w) : 0.f;
            float p10 = nib1 & 1 ? fmaxf(aA1 * e1.x, bB1 * e2.x) : 0.f;
            float p11 = nib1 & 2 ? fmaxf(aA1 * e1.y, bB1 * e2.y) : 0.f;
            float p12 = nib1 & 4 ? fmaxf(aA1 * e1.z, bB1 * e2.z) : 0.f;
            float p13 = nib1 & 8 ? fmaxf(aA1 * e1.w, bB1 * e2.w) : 0.f;

            stcs4(attn0 + j, p00, p01, p02, p03);
            stcs4(attn1 + j, p10, p11, p12, p13);

            ah[kk][0] = packh2(p00, p01);   // row g,   k-pair 2tq
            ah[kk][1] = packh2(p10, p11);   // row g+8, k-pair 2tq
            ah[kk][2] = packh2(p02, p03);   // row g,   k-pair 2tq+8
            ah[kk][3] = packh2(p12, p13);   // row g+8, k-pair 2tq+8
        }

        // ---- Phase B: kk-outer/np-inner, flattened 1-deep LDSM prefetch ----
        const uint32_t lmb = smb + buf * VERBYTES + lmoff;
        uint32_t b0, b1, b2, b3;
        LDMX4(b0, b1, b2, b3, lmb);        // (kk=0, np=0)
#pragma unroll
        for (int it = 0; it < 64; it++) {
            const int kk = it >> 3, np = it & 7;
            uint32_t n0, n1, n2, n3;
            if (it < 63) {
                const int itn = it + 1;
                LDMX4(n0, n1, n2, n3,
                      lmb + (itn & 7) * (16 * ROWSTRIDE) + (itn >> 3) * 32);
            }
            MMA16816(acc[2 * np],     ah[kk][0], ah[kk][1], ah[kk][2], ah[kk][3], b0, b1);
            MMA16816(acc[2 * np + 1], ah[kk][0], ah[kk][1], ah[kk][2], ah[kk][3], b2, b3);
            if (it < 63) { b0 = n0; b1 = n1; b2 = n2; b3 = n3; }
        }
        __syncthreads();
    }

    // epilogue: h_prime partial for this j-third
    float* __restrict__ part = g_part + (size_t)js * KN * OUTF;
#pragma unroll
    for (int nt = 0; nt < 16; nt++) {
        int cc = nt * 8 + 2 * tq;
        *(float2*)(part + (size_t)row0 * OUTF + cc) = make_float2(acc[nt].x, acc[nt].y);
        *(float2*)(part + (size_t)row1 * OUTF + cc) = make_float2(acc[nt].z, acc[nt].w);
    }
}

// ---------------- K3: reduce partials ----------------
__global__ void __launch_bounds__(256) k_red(float* __restrict__ out) {
    const size_t SZ = (size_t)KN * OUTF;
    size_t idx = ((size_t)blockIdx.x * 256 + threadIdx.x) * 4;
    float4 a = *(const float4*)(g_part + idx);
    float4 b = *(const float4*)(g_part + SZ + idx);
    float4 c = *(const float4*)(g_part + 2 * SZ + idx);
    *(float4*)(out + idx) = make_float4(a.x + b.x + c.x, a.y + b.y + c.y,
                                        a.z + b.z + c.z, a.w + b.w + c.w);
}

extern "C" void kernel_launch(void* const* d_in, const int* in_sizes, int n_in,
                              void* d_out, int out_size) {
    const float* h   = (const float*)d_in[0];
    const int*   adj = (const int*)d_in[1];
    const float* W   = (const float*)d_in[2];
    const float* a   = (const float*)d_in[3];
    float* out = (float*)d_out;

    cudaFuncSetAttribute(k_main, cudaFuncAttributeMaxDynamicSharedMemorySize, SMEM_MAIN);

    k_pre<<<KN / 8, 256>>>(h, W, a);
    k_bits<<<KN / 8, 256>>>(adj);
    k_main<<<(KN / 128) * NSPLIT, 256, SMEM_MAIN>>>(out);
    k_red<<<(KN * OUTF) / (256 * 4), 256>>>(out);
}

// round 13
// speedup vs baseline: 1.2735x; 1.0724x over previous
#include <cuda_runtime.h>
#include <cuda_fp16.h>
#include <cstdint>

// GraphAttentionLayer: N=12288, IN_F=256, OUT_F=128, slope=0.2
// out = [h_prime (N x 128) | attention (N x N)] fp32.
//
//  k_pre    : h_t = h @ W in regs -> htT fp16 (transposed, k-PERMUTED) + exp
//             tables.
//  k_bits   : adj -> packed bitmask + folded denominators (flat, __ldcs).
//  k_main   : grid 288 = 96 row-tiles x 3 j-thirds, 256 thr, 2 blocks/SM;
//             kk-granular software pipeline: fragment-gen for kk+1 (incl.
//             attention stores) interleaved inside kk's MMA sweep, ping-pong
//             frag regs; B via cp.async double-buffer + ldmatrix.
//  k_red    : sum 3 partials -> h_prime.

#define KN    12288
#define INF_  256
#define OUTF  128
#define NWORDS (KN / 32)     // 384
#define CH    128            // K-chunk
#define NSPLIT 3
#define NCL   (KN / CH / NSPLIT)   // 32 chunks per split
#define JSPAN (KN / NSPLIT)        // 4096

__device__ __half g_htT[(size_t)OUTF * KN];   // k-permuted layout
__device__ __align__(16) float g_Es[KN], g_Es2[KN], g_Etgt[KN], g_Etgt2[KN];
__device__ float g_A[KN], g_B[KN];
__device__ __align__(16) uint32_t g_bits[(size_t)KN * NWORDS];
__device__ float g_part[(size_t)NSPLIT * KN * OUTF];

// ---------------- helpers ----------------
__device__ __forceinline__ uint32_t smem_u32(const void* p) {
    uint32_t a;
    asm("{ .reg .u64 t; cvta.to.shared.u64 t, %1; cvt.u32.u64 %0, t; }" : "=r"(a) : "l"(p));
    return a;
}
__device__ __forceinline__ uint32_t packh2(float p0, float p1) {
    uint32_t r;
    asm("cvt.rn.f16x2.f32 %0, %1, %2;" : "=r"(r) : "f"(p1), "f"(p0));
    return r;
}
__device__ __forceinline__ void stcs4(float* p, float a, float b, float c, float d) {
    asm volatile("st.global.cs.v4.f32 [%0], {%1, %2, %3, %4};"
                 :: "l"(p), "f"(a), "f"(b), "f"(c), "f"(d));
}

#define MMA16816(d, a0, a1, a2, a3, b0, b1) \
    asm volatile( \
        "mma.sync.aligned.m16n8k16.row.col.f32.f16.f16.f32 " \
        "{%0,%1,%2,%3}, {%4,%5,%6,%7}, {%8,%9}, {%0,%1,%2,%3};" \
        : "+f"((d).x), "+f"((d).y), "+f"((d).z), "+f"((d).w) \
        : "r"(a0), "r"(a1), "r"(a2), "r"(a3), "r"(b0), "r"(b1))

#define LDMX4(r0, r1, r2, r3, ad) \
    asm volatile("ldmatrix.sync.aligned.m8n8.x4.shared.b16 {%0,%1,%2,%3}, [%4];" \
                 : "=r"(r0), "=r"(r1), "=r"(r2), "=r"(r3) : "r"(ad))

#define CP16(dst, src) \
    asm volatile("cp.async.cg.shared.global [%0], [%1], 16;" :: "r"(dst), "l"(src) : "memory")
#define CP_COMMIT() asm volatile("cp.async.commit_group;" ::: "memory")
#define CP_WAIT1()  asm volatile("cp.async.wait_group 1;" ::: "memory")
#define CP_WAIT0()  asm volatile("cp.async.wait_group 0;" ::: "memory")

// ---------------- K1: fused h@W -> permuted htT fp16 + exp tables -----------
__global__ void __launch_bounds__(256) k_pre(const float* __restrict__ h,
                                             const float* __restrict__ W,
                                             const float* __restrict__ a) {
    __shared__ float h_s[8 * INF_];
    __shared__ float red[8][8];
    int t = threadIdx.x;
    int r0 = blockIdx.x * 8;
    for (int idx = t; idx < 8 * INF_; idx += 256)
        h_s[idx] = h[(size_t)r0 * INF_ + idx];
    __syncthreads();
    int c  = t & 127;
    int rg = t >> 7;
    float acc[4] = {0.f, 0.f, 0.f, 0.f};
    for (int k = 0; k < INF_; k++) {
        float w = W[k * OUTF + c];
#pragma unroll
        for (int rr = 0; rr < 4; rr++)
            acc[rr] = fmaf(h_s[(rg * 4 + rr) * INF_ + k], w, acc[rr]);
    }
    // permuted store: 4 consecutive j (= one t-group) -> k-pairs {2T, 2T+8}
    {
        int jj  = r0 + rg * 4;
        int grp = jj & ~15;
        int T   = (jj & 15) >> 2;
        __half* dst = g_htT + (size_t)c * KN + grp;
        *(uint32_t*)(dst + 2 * T)     = packh2(acc[0], acc[1]);
        *(uint32_t*)(dst + 2 * T + 8) = packh2(acc[2], acc[3]);
    }

    float av = a[c], av2 = a[OUTF + c];
    float s[8];
#pragma unroll
    for (int rr = 0; rr < 4; rr++) {
        s[rr * 2]     = acc[rr] * av;
        s[rr * 2 + 1] = acc[rr] * av2;
    }
#pragma unroll
    for (int o = 16; o > 0; o >>= 1)
#pragma unroll
        for (int i = 0; i < 8; i++)
            s[i] += __shfl_down_sync(0xFFFFFFFFu, s[i], o);
    int w = t >> 5, l = t & 31;
    if (l == 0)
#pragma unroll
        for (int i = 0; i < 8; i++) red[w][i] = s[i];
    __syncthreads();
    if (t < 16) {
        int rho = t >> 1, which = t & 1;
        int rg2 = rho >> 2, rr = rho & 3;
        float v = red[rg2 * 4 + 0][rr * 2 + which] + red[rg2 * 4 + 1][rr * 2 + which]
                + red[rg2 * 4 + 2][rr * 2 + which] + red[rg2 * 4 + 3][rr * 2 + which];
        int r = r0 + rho;
        if (which == 0) { g_Es[r]   = expf(v); g_Es2[r]   = expf(0.2f * v); }
        else            { g_Etgt[r] = expf(v); g_Etgt2[r] = expf(0.2f * v); }
    }
}

// ---------------- Kbits: bitmask + denominators (flat, schedulable loads) ---
__global__ void __launch_bounds__(256) k_bits(const int* __restrict__ adj) {
    int t = threadIdx.x;
    int l = t & 31;
    int r = blockIdx.x * 8 + (t >> 5);
    float Es = g_Es[r], Es2 = g_Es2[r];
    const int4* __restrict__ arow = (const int4*)(adj + (size_t)r * KN);
    uint32_t* __restrict__ brow = g_bits + (size_t)r * NWORDS;
    const int sh = (l & 7) * 4;
    float ls0 = 0.f, ls1 = 0.f, ls2 = 0.f, ls3 = 0.f;

#pragma unroll 8
    for (int it = 0; it < KN / 128; it++) {     // 96 iterations, 128 j per warp
        int j = it * 128 + l * 4;
        int4 m = __ldcs(arow + it * 32 + l);    // intrinsic: compiler can batch
        float4 e1 = *(const float4*)(g_Etgt + j);
        float4 e2 = *(const float4*)(g_Etgt2 + j);
        uint32_t nib = 0;
        if (m.x) { nib |= 1u; ls0 += fmaxf(Es * e1.x, Es2 * e2.x); }
        if (m.y) { nib |= 2u; ls1 += fmaxf(Es * e1.y, Es2 * e2.y); }
        if (m.z) { nib |= 4u; ls2 += fmaxf(Es * e1.z, Es2 * e2.z); }
        if (m.w) { nib |= 8u; ls3 += fmaxf(Es * e1.w, Es2 * e2.w); }
        uint32_t word = nib << sh;
        word |= __shfl_xor_sync(0xFFFFFFFFu, word, 1);
        word |= __shfl_xor_sync(0xFFFFFFFFu, word, 2);
        word |= __shfl_xor_sync(0xFFFFFFFFu, word, 4);
        if ((l & 7) == 0) brow[it * 4 + (l >> 3)] = word;
    }
    float lsum = (ls0 + ls1) + (ls2 + ls3);
#pragma unroll
    for (int o = 16; o > 0; o >>= 1) lsum += __shfl_down_sync(0xFFFFFFFFu, lsum, o);
    if (l == 0) {
        float inv = 1.0f / lsum;
        g_A[r] = Es * inv;
        g_B[r] = Es2 * inv;
    }
}

// ---------------- K2: fused P-gen + mma.sync GEMM (kk-pipelined) --------
#define ROWSTRIDE 272
#define VERBYTES  (128 * ROWSTRIDE)   // 34816
#define SMEM_MAIN (2 * VERBYTES)      // 69632

// generate 4 contiguous-j P values for one kk, store attention, pack frags
#define GEN_KK(JLOC, WORD0, WORD1, DST) do {                                  \
    const int j_ = jbase + (JLOC) + 4 * tq;                                   \
    float4 e1 = *(const float4*)(g_Etgt  + j_);                               \
    float4 e2 = *(const float4*)(g_Etgt2 + j_);                               \
    const uint32_t nib0 = (WORD0) >> (4 * tq);                                \
    const uint32_t nib1 = (WORD1) >> (4 * tq);                                \
    float p00 = nib0 & 1 ? fmaxf(aA0 * e1.x, bB0 * e2.x) : 0.f;               \
    float p01 = nib0 & 2 ? fmaxf(aA0 * e1.y, bB0 * e2.y) : 0.f;               \
    float p02 = nib0 & 4 ? fmaxf(aA0 * e1.z, bB0 * e2.z) : 0.f;               \
    float p03 = nib0 & 8 ? fmaxf(aA0 * e1.w, bB0 * e2.w) : 0.f;               \
    float p10 = nib1 & 1 ? fmaxf(aA1 * e1.x, bB1 * e2.x) : 0.f;               \
    float p11 = nib1 & 2 ? fmaxf(aA1 * e1.y, bB1 * e2.y) : 0.f;               \
    float p12 = nib1 & 4 ? fmaxf(aA1 * e1.z, bB1 * e2.z) : 0.f;               \
    float p13 = nib1 & 8 ? fmaxf(aA1 * e1.w, bB1 * e2.w) : 0.f;               \
    stcs4(attn0 + j_, p00, p01, p02, p03);                                    \
    stcs4(attn1 + j_, p10, p11, p12, p13);                                    \
    (DST)[0] = packh2(p00, p01);                                              \
    (DST)[1] = packh2(p10, p11);                                              \
    (DST)[2] = packh2(p02, p03);                                              \
    (DST)[3] = packh2(p12, p13);                                              \
} while (0)

__global__ void __launch_bounds__(256, 2) k_main(float* __restrict__ out) {
    extern __shared__ char sm[];
    const uint32_t smb = smem_u32(sm);
    const int t  = threadIdx.x;
    const int w  = t >> 5, l = t & 31;
    const int g  = l >> 2, tq = l & 3;
    const int ti = blockIdx.x / NSPLIT;     // row tile
    const int js = blockIdx.x % NSPLIT;     // j third
    const int i0 = ti * 128;
    const int jbase = js * JSPAN;
    const int row0 = i0 + w * 16 + g;       // warp owns 16 rows
    const int row1 = row0 + 8;

    const float aA0 = g_A[row0], bB0 = g_B[row0];
    const float aA1 = g_A[row1], bB1 = g_B[row1];
    float* __restrict__ attn0 = out + (size_t)KN * OUTF + (size_t)row0 * KN;
    float* __restrict__ attn1 = out + (size_t)KN * OUTF + (size_t)row1 * KN;
    const uint32_t* __restrict__ bw0 = g_bits + (size_t)row0 * NWORDS + js * NCL * 4;
    const uint32_t* __restrict__ bw1 = g_bits + (size_t)row1 * NWORDS + js * NCL * 4;

    const int cpr = t >> 4;          // 0..15
    const int cpk = t & 15;
    const uint32_t lmrow = ((l >> 4) & 1) * 8 + (l & 7);
    const uint32_t lmoff = lmrow * ROWSTRIDE + ((l >> 3) & 1) * 16;

    float4 acc[16];
#pragma unroll
    for (int i = 0; i < 16; i++) acc[i] = make_float4(0.f, 0.f, 0.f, 0.f);

    // prologue: chunk 0 -> buf 0
#pragma unroll
    for (int i = 0; i < 8; i++) {
        int row = cpr + i * 16;
        CP16(smb + row * ROWSTRIDE + cpk * 16,
             g_htT + (size_t)row * KN + jbase + cpk * 8);
    }
    CP_COMMIT();

    // prologue: generate fragments for (chunk 0, kk 0)
    uint32_t ahP[2][4];
    {
        const uint32_t x0 = bw0[0], x1 = bw1[0];
        GEN_KK(0, x0, x1, ahP[0]);
    }

    for (int c = 0; c < NCL; c++) {
        const int buf = c & 1;
        // bits for this chunk (kk 1..7 gens) + next chunk's first word
        const uint4 w0 = *(const uint4*)(bw0 + c * 4);
        const uint4 w1 = *(const uint4*)(bw1 + c * 4);
        const int more = (c + 1 < NCL);
        const uint32_t nx0 = more ? bw0[(c + 1) * 4] : 0u;
        const uint32_t nx1 = more ? bw1[(c + 1) * 4] : 0u;

        if (more) {
            const int jn = jbase + (c + 1) * CH;
            const uint32_t dstb = smb + (buf ^ 1) * VERBYTES;
#pragma unroll
            for (int i = 0; i < 8; i++) {
                int row = cpr + i * 16;
                CP16(dstb + row * ROWSTRIDE + cpk * 16,
                     g_htT + (size_t)row * KN + jn + cpk * 8);
            }
            CP_COMMIT();
            CP_WAIT1();
        } else {
            CP_WAIT0();
        }
        __syncthreads();

        const uint32_t lmb = smb + buf * VERBYTES + lmoff;
        uint32_t b0, b1, b2, b3;
        LDMX4(b0, b1, b2, b3, lmb);        // (kk=0, np=0)
#pragma unroll
        for (int it = 0; it < 64; it++) {
            const int kk = it >> 3, np = it & 7;
            uint32_t n0, n1, n2, n3;
            if (it < 63) {
                const int itn = it + 1;
                LDMX4(n0, n1, n2, n3,
                      lmb + (itn & 7) * (16 * ROWSTRIDE) + (itn >> 3) * 32);
            }
            MMA16816(acc[2 * np],     ahP[kk & 1][0], ahP[kk & 1][1],
                                      ahP[kk & 1][2], ahP[kk & 1][3], b0, b1);
            MMA16816(acc[2 * np + 1], ahP[kk & 1][0], ahP[kk & 1][1],
                                      ahP[kk & 1][2], ahP[kk & 1][3], b2, b3);
            // interleaved fragment-gen for kk+1 (or next chunk's kk0)
            if (np == 2) {
                if (kk < 7) {
                    const uint32_t x0 = ((const uint32_t*)&w0)[(kk + 1) >> 1] >> (((kk + 1) & 1) * 16);
                    const uint32_t x1 = ((const uint32_t*)&w1)[(kk + 1) >> 1] >> (((kk + 1) & 1) * 16);
                    GEN_KK(c * CH + (kk + 1) * 16, x0, x1, ahP[(kk + 1) & 1]);
                } else if (more) {
                    GEN_KK((c + 1) * CH, nx0, nx1, ahP[0]);
                }
            }
            if (it < 63) { b0 = n0; b1 = n1; b2 = n2; b3 = n3; }
        }
        __syncthreads();
    }

    // epilogue: h_prime partial for this j-third
    float* __restrict__ part = g_part + (size_t)js * KN * OUTF;
#pragma unroll
    for (int nt = 0; nt < 16; nt++) {
        int cc = nt * 8 + 2 * tq;
        *(float2*)(part + (size_t)row0 * OUTF + cc) = make_float2(acc[nt].x, acc[nt].y);
        *(float2*)(part + (size_t)row1 * OUTF + cc) = make_float2(acc[nt].z, acc[nt].w);
    }
}

// ---------------- K3: reduce partials ----------------
__global__ void __launch_bounds__(256) k_red(float* __restrict__ out) {
    const size_t SZ = (size_t)KN * OUTF;
    size_t idx = ((size_t)blockIdx.x * 256 + threadIdx.x) * 4;
    float4 a = *(const float4*)(g_part + idx);
    float4 b = *(const float4*)(g_part + SZ + idx);
    float4 c = *(const float4*)(g_part + 2 * SZ + idx);
    *(float4*)(out + idx) = make_float4(a.x + b.x + c.x, a.y + b.y + c.y,
                                        a.z + b.z + c.z, a.w + b.w + c.w);
}

extern "C" void kernel_launch(void* const* d_in, const int* in_sizes, int n_in,
                              void* d_out, int out_size) {
    const float* h   = (const float*)d_in[0];
    const int*   adj = (const int*)d_in[1];
    const float* W   = (const float*)d_in[2];
    const float* a   = (const float*)d_in[3];
    float* out = (float*)d_out;

    cudaFuncSetAttribute(k_main, cudaFuncAttributeMaxDynamicSharedMemorySize, SMEM_MAIN);

    k_pre<<<KN / 8, 256>>>(h, W, a);
    k_bits<<<KN / 8, 256>>>(adj);
    k_main<<<(KN / 128) * NSPLIT, 256, SMEM_MAIN>>>(out);
    k_red<<<(KN * OUTF) / (256 * 4), 256>>>(out);
}